// round 12
// baseline (speedup 1.0000x reference)
#include <cuda_runtime.h>
#include <cstdint>

// Problem constants
#define H_   128
#define W_   256
#define C_   128
#define B_   8
#define HW_  (H_ * W_)
#define CHW_ (C_ * HW_)

// Tiling
#define TH   8              // output rows per block
#define TW   32             // output cols per block
#define PW   8              // pixels per thread (along w)
#define NDY  9              // dy values (threadIdx.y)
#define CC   8              // channels per chunk (halved: fit 2 CTAs/SM)
#define NC   (C_ / CC)      // 16 chunks
#define X2H  (TH + 8)       // 16 x2 rows in tile
#define X2W  52             // 48 data cols + 4 pad (52 mod 32 = 20 -> conflict-free rows)
#define S1   (CC * TH * TW)          // x1 tile floats  = 2048
#define S2   (CC * X2H * X2W)        // x2 tile floats  = 6656
#define BUFF (S1 + S2)               // 8704 floats per buffer
#define SMEM_BYTES (2 * BUFF * 4)    // 69632 B (double buffered) -> 2 CTAs/SM
#define NTHREADS 288

typedef unsigned long long ull;

__device__ __forceinline__ ull pk2(float lo, float hi) {
    ull r;
    asm("mov.b64 %0, {%1, %2};"
        : "=l"(r) : "r"(__float_as_uint(lo)), "r"(__float_as_uint(hi)));
    return r;
}
__device__ __forceinline__ void fma2(ull& d, ull a, ull b) {
    // packed f32x2 FMA: d.lo += a.lo*b.lo ; d.hi += a.hi*b.hi
    asm("fma.rn.f32x2 %0, %1, %2, %0;" : "+l"(d) : "l"(a), "l"(b));
}
__device__ __forceinline__ void upk2(ull v, float& lo, float& hi) {
    unsigned l, h;
    asm("mov.b64 {%0, %1}, %2;" : "=r"(l), "=r"(h) : "l"(v));
    lo = __uint_as_float(l); hi = __uint_as_float(h);
}
__device__ __forceinline__ void cp16(unsigned sdst, const float* g, bool valid) {
    int sz = valid ? 16 : 0;   // src-size 0 => zero-fill 16B (zfill pattern)
    asm volatile("cp.async.cg.shared.global [%0], [%1], 16, %2;"
                 :: "r"(sdst), "l"(g), "r"(sz));
}

__global__ void __launch_bounds__(NTHREADS, 2)
corr_kernel(const float* __restrict__ x1, const float* __restrict__ x2,
            float* __restrict__ out)
{
    extern __shared__ float smem[];

    const int b  = blockIdx.z;
    const int h0 = blockIdx.y * TH;
    const int w0 = blockIdx.x * TW;
    const int wg = threadIdx.x;   // 0..3  : group of 8 pixels along w
    const int dy = threadIdx.y;   // 0..8  : vertical displacement index
    const int hz = threadIdx.z;   // 0..7  : row within tile
    const int tid = wg + 4 * dy + 36 * hz;

    const unsigned smem_u = (unsigned)__cvta_generic_to_shared(smem);

    // ---- loader role setup (chunk-invariant) ----
    // tid <  192 : x2 loader, one (row, col4) slot, loops over CC channels
    // 192..255   : x1 loader
    const bool isX2 = (tid < 192);
    const bool isX1 = (tid >= 192) && (tid < 256);
    int  l_goff = 0, l_soff = 0;
    bool l_valid = false;
    if (isX2) {
        int r  = tid / 12, c4 = tid % 12;
        int gh = h0 - 4 + r;
        int gw = w0 - 8 + c4 * 4;          // tile starts at w0-8 for 16B alignment
        l_valid = (gh >= 0) && (gh < H_) && (gw >= 0) && (gw < W_);
        l_goff  = l_valid ? (b * CHW_ + gh * W_ + gw) : 0;
        l_soff  = r * X2W + c4 * 4;
    } else if (isX1) {
        int t  = tid - 192;
        int r  = t >> 3, c4 = t & 7;
        l_goff = b * CHW_ + (h0 + r) * W_ + w0 + c4 * 4;
        l_soff = r * TW + c4 * 4;
        l_valid = true;
    }

    auto issue = [&](int k, int bsel) {
        if (isX2) {
            const float* g = x2 + (size_t)k * CC * HW_ + l_goff;
            unsigned s = smem_u + (unsigned)((bsel * BUFF + S1 + l_soff) * 4);
            #pragma unroll
            for (int c = 0; c < CC; ++c)
                cp16(s + (unsigned)(c * (X2H * X2W * 4)), g + (size_t)c * HW_, l_valid);
        } else if (isX1) {
            const float* g = x1 + (size_t)k * CC * HW_ + l_goff;
            unsigned s = smem_u + (unsigned)((bsel * BUFF + l_soff) * 4);
            #pragma unroll
            for (int c = 0; c < CC; ++c)
                cp16(s + (unsigned)(c * (TH * TW * 4)), g + (size_t)c * HW_, true);
        }
        asm volatile("cp.async.commit_group;");
    };

    // ---- accumulators: 9 dx * 4 pixel-pairs (f32x2) ----
    ull acc[36];
    #pragma unroll
    for (int i = 0; i < 36; ++i) acc[i] = 0ull;

    issue(0, 0);

    const int arow = hz * TW + wg * 8;                 // x1 smem offset (per channel)
    const int brow = (hz + dy) * X2W + 4 + wg * 8;     // x2 smem offset (+4: tile starts w0-8)

    #pragma unroll 1
    for (int k = 0; k < NC; ++k) {
        if (k + 1 < NC) issue(k + 1, (k + 1) & 1);
        if (k + 1 < NC) asm volatile("cp.async.wait_group 1;");
        else            asm volatile("cp.async.wait_group 0;");
        __syncthreads();

        const float* s1p = smem + (k & 1) * BUFF;
        const float* s2p = s1p + S1;

        #pragma unroll
        for (int c = 0; c < CC; ++c) {
            float4 a0 = *(const float4*)(s1p + c * (TH * TW) + arow);
            float4 a1 = *(const float4*)(s1p + c * (TH * TW) + arow + 4);
            const float* br = s2p + c * (X2H * X2W) + brow;
            float4 b0 = *(const float4*)(br);
            float4 b1 = *(const float4*)(br + 4);
            float4 b2 = *(const float4*)(br + 8);
            float4 b3 = *(const float4*)(br + 12);
            float bx[16] = { b0.x, b0.y, b0.z, b0.w,  b1.x, b1.y, b1.z, b1.w,
                             b2.x, b2.y, b2.z, b2.w,  b3.x, b3.y, b3.z, b3.w };

            ull A0 = pk2(a0.x, a0.y), A1 = pk2(a0.z, a0.w);
            ull A2 = pk2(a1.x, a1.y), A3 = pk2(a1.z, a1.w);
            ull BP[15];
            #pragma unroll
            for (int j = 0; j < 15; ++j) BP[j] = pk2(bx[j], bx[j + 1]);

            // acc[dx*4+p] covers pixels (2p, 2p+1); b-pair starts at bx[2p+dx]
            #pragma unroll
            for (int dx = 0; dx < 9; ++dx) {
                fma2(acc[dx * 4 + 0], A0, BP[dx + 0]);
                fma2(acc[dx * 4 + 1], A1, BP[dx + 2]);
                fma2(acc[dx * 4 + 2], A2, BP[dx + 4]);
                fma2(acc[dx * 4 + 3], A3, BP[dx + 6]);
            }
        }
        __syncthreads();
    }

    // ---- epilogue: mean over C, LeakyReLU(0.1), store ----
    const float inv = 1.0f / 128.0f;
    const int h  = h0 + hz;
    const int wb = w0 + wg * 8;
    #pragma unroll
    for (int dx = 0; dx < 9; ++dx) {
        const int d = dy * 9 + dx;
        float r[8];
        #pragma unroll
        for (int p = 0; p < 4; ++p) {
            float lo, hi;
            upk2(acc[dx * 4 + p], lo, hi);
            lo *= inv; hi *= inv;
            r[2 * p]     = (lo > 0.0f) ? lo : 0.1f * lo;
            r[2 * p + 1] = (hi > 0.0f) ? hi : 0.1f * hi;
        }
        float4* op = (float4*)(out + (size_t)((b * 81 + d) * H_ + h) * W_ + wb);
        op[0] = make_float4(r[0], r[1], r[2], r[3]);
        op[1] = make_float4(r[4], r[5], r[6], r[7]);
    }
}

extern "C" void kernel_launch(void* const* d_in, const int* in_sizes, int n_in,
                              void* d_out, int out_size)
{
    const float* x1 = (const float*)d_in[0];
    const float* x2 = (const float*)d_in[1];
    float* out = (float*)d_out;

    cudaFuncSetAttribute(corr_kernel,
                         cudaFuncAttributeMaxDynamicSharedMemorySize, SMEM_BYTES);

    dim3 grid(W_ / TW, H_ / TH, B_);   // (8, 16, 8) = 1024 blocks
    dim3 block(4, NDY, TH);            // 288 threads
    corr_kernel<<<grid, block, SMEM_BYTES>>>(x1, x2, out);
}

// round 13
// speedup vs baseline: 1.0028x; 1.0028x over previous
#include <cuda_runtime.h>
#include <cstdint>

// Problem constants
#define H_   128
#define W_   256
#define C_   128
#define B_   8
#define HW_  (H_ * W_)
#define CHW_ (C_ * HW_)

// Tiling
#define TH   8              // output rows per block
#define TW   32             // output cols per block
#define PW   8              // pixels per thread (along w)
#define NDY  9              // dy values (threadIdx.y)
#define CC   8              // channels per chunk (halved: fit 2 CTAs/SM)
#define NC   (C_ / CC)      // 16 chunks
#define X2H  (TH + 8)       // 16 x2 rows in tile
#define X2W  52             // 48 data cols + 4 pad (52 mod 32 = 20 -> conflict-free rows)
#define S1   (CC * TH * TW)          // x1 tile floats  = 2048
#define S2   (CC * X2H * X2W)        // x2 tile floats  = 6656
#define BUFF (S1 + S2)               // 8704 floats per buffer
#define SMEM_BYTES (2 * BUFF * 4)    // 69632 B (double buffered) -> 2 CTAs/SM
#define NTHREADS 288

typedef unsigned long long ull;

__device__ __forceinline__ ull pk2(float lo, float hi) {
    ull r;
    asm("mov.b64 %0, {%1, %2};"
        : "=l"(r) : "r"(__float_as_uint(lo)), "r"(__float_as_uint(hi)));
    return r;
}
__device__ __forceinline__ void fma2(ull& d, ull a, ull b) {
    // packed f32x2 FMA: d.lo += a.lo*b.lo ; d.hi += a.hi*b.hi
    asm("fma.rn.f32x2 %0, %1, %2, %0;" : "+l"(d) : "l"(a), "l"(b));
}
__device__ __forceinline__ void upk2(ull v, float& lo, float& hi) {
    unsigned l, h;
    asm("mov.b64 {%0, %1}, %2;" : "=r"(l), "=r"(h) : "l"(v));
    lo = __uint_as_float(l); hi = __uint_as_float(h);
}
__device__ __forceinline__ void cp16(unsigned sdst, const float* g, bool valid) {
    int sz = valid ? 16 : 0;   // src-size 0 => zero-fill 16B (zfill pattern)
    asm volatile("cp.async.cg.shared.global [%0], [%1], 16, %2;"
                 :: "r"(sdst), "l"(g), "r"(sz));
}

__global__ void __launch_bounds__(NTHREADS, 2)
corr_kernel(const float* __restrict__ x1, const float* __restrict__ x2,
            float* __restrict__ out)
{
    extern __shared__ float smem[];

    const int b  = blockIdx.z;
    const int h0 = blockIdx.y * TH;
    const int w0 = blockIdx.x * TW;
    const int wg = threadIdx.x;   // 0..3  : group of 8 pixels along w
    const int dy = threadIdx.y;   // 0..8  : vertical displacement index
    const int hz = threadIdx.z;   // 0..7  : row within tile
    const int tid = wg + 4 * dy + 36 * hz;

    const unsigned smem_u = (unsigned)__cvta_generic_to_shared(smem);

    // ---- loader role setup (chunk-invariant) ----
    // tid <  192 : x2 loader, one (row, col4) slot, loops over CC channels
    // 192..255   : x1 loader
    const bool isX2 = (tid < 192);
    const bool isX1 = (tid >= 192) && (tid < 256);
    int  l_goff = 0, l_soff = 0;
    bool l_valid = false;
    if (isX2) {
        int r  = tid / 12, c4 = tid % 12;
        int gh = h0 - 4 + r;
        int gw = w0 - 8 + c4 * 4;          // tile starts at w0-8 for 16B alignment
        l_valid = (gh >= 0) && (gh < H_) && (gw >= 0) && (gw < W_);
        l_goff  = l_valid ? (b * CHW_ + gh * W_ + gw) : 0;
        l_soff  = r * X2W + c4 * 4;
    } else if (isX1) {
        int t  = tid - 192;
        int r  = t >> 3, c4 = t & 7;
        l_goff = b * CHW_ + (h0 + r) * W_ + w0 + c4 * 4;
        l_soff = r * TW + c4 * 4;
        l_valid = true;
    }

    auto issue = [&](int k, int bsel) {
        if (isX2) {
            const float* g = x2 + (size_t)k * CC * HW_ + l_goff;
            unsigned s = smem_u + (unsigned)((bsel * BUFF + S1 + l_soff) * 4);
            #pragma unroll
            for (int c = 0; c < CC; ++c)
                cp16(s + (unsigned)(c * (X2H * X2W * 4)), g + (size_t)c * HW_, l_valid);
        } else if (isX1) {
            const float* g = x1 + (size_t)k * CC * HW_ + l_goff;
            unsigned s = smem_u + (unsigned)((bsel * BUFF + l_soff) * 4);
            #pragma unroll
            for (int c = 0; c < CC; ++c)
                cp16(s + (unsigned)(c * (TH * TW * 4)), g + (size_t)c * HW_, true);
        }
        asm volatile("cp.async.commit_group;");
    };

    // ---- accumulators: 9 dx * 4 pixel-pairs (f32x2) ----
    ull acc[36];
    #pragma unroll
    for (int i = 0; i < 36; ++i) acc[i] = 0ull;

    issue(0, 0);

    const int arow = hz * TW + wg * 8;                 // x1 smem offset (per channel)
    const int brow = (hz + dy) * X2W + 4 + wg * 8;     // x2 smem offset (+4: tile starts w0-8)

    #pragma unroll 1
    for (int k = 0; k < NC; ++k) {
        if (k + 1 < NC) issue(k + 1, (k + 1) & 1);
        if (k + 1 < NC) asm volatile("cp.async.wait_group 1;");
        else            asm volatile("cp.async.wait_group 0;");
        __syncthreads();

        const float* s1p = smem + (k & 1) * BUFF;
        const float* s2p = s1p + S1;

        #pragma unroll
        for (int c = 0; c < CC; ++c) {
            float4 a0 = *(const float4*)(s1p + c * (TH * TW) + arow);
            float4 a1 = *(const float4*)(s1p + c * (TH * TW) + arow + 4);
            const float* br = s2p + c * (X2H * X2W) + brow;
            float4 b0 = *(const float4*)(br);
            float4 b1 = *(const float4*)(br + 4);
            float4 b2 = *(const float4*)(br + 8);
            float4 b3 = *(const float4*)(br + 12);
            float bx[16] = { b0.x, b0.y, b0.z, b0.w,  b1.x, b1.y, b1.z, b1.w,
                             b2.x, b2.y, b2.z, b2.w,  b3.x, b3.y, b3.z, b3.w };

            ull A0 = pk2(a0.x, a0.y), A1 = pk2(a0.z, a0.w);
            ull A2 = pk2(a1.x, a1.y), A3 = pk2(a1.z, a1.w);
            ull BP[15];
            #pragma unroll
            for (int j = 0; j < 15; ++j) BP[j] = pk2(bx[j], bx[j + 1]);

            // acc[dx*4+p] covers pixels (2p, 2p+1); b-pair starts at bx[2p+dx]
            #pragma unroll
            for (int dx = 0; dx < 9; ++dx) {
                fma2(acc[dx * 4 + 0], A0, BP[dx + 0]);
                fma2(acc[dx * 4 + 1], A1, BP[dx + 2]);
                fma2(acc[dx * 4 + 2], A2, BP[dx + 4]);
                fma2(acc[dx * 4 + 3], A3, BP[dx + 6]);
            }
        }
        __syncthreads();
    }

    // ---- epilogue: mean over C, LeakyReLU(0.1), store ----
    const float inv = 1.0f / 128.0f;
    const int h  = h0 + hz;
    const int wb = w0 + wg * 8;
    #pragma unroll
    for (int dx = 0; dx < 9; ++dx) {
        const int d = dy * 9 + dx;
        float r[8];
        #pragma unroll
        for (int p = 0; p < 4; ++p) {
            float lo, hi;
            upk2(acc[dx * 4 + p], lo, hi);
            lo *= inv; hi *= inv;
            r[2 * p]     = (lo > 0.0f) ? lo : 0.1f * lo;
            r[2 * p + 1] = (hi > 0.0f) ? hi : 0.1f * hi;
        }
        float4* op = (float4*)(out + (size_t)((b * 81 + d) * H_ + h) * W_ + wb);
        op[0] = make_float4(r[0], r[1], r[2], r[3]);
        op[1] = make_float4(r[4], r[5], r[6], r[7]);
    }
}

extern "C" void kernel_launch(void* const* d_in, const int* in_sizes, int n_in,
                              void* d_out, int out_size)
{
    const float* x1 = (const float*)d_in[0];
    const float* x2 = (const float*)d_in[1];
    float* out = (float*)d_out;

    cudaFuncSetAttribute(corr_kernel,
                         cudaFuncAttributeMaxDynamicSharedMemorySize, SMEM_BYTES);

    dim3 grid(W_ / TW, H_ / TH, B_);   // (8, 16, 8) = 1024 blocks
    dim3 block(4, NDY, TH);            // 288 threads
    corr_kernel<<<grid, block, SMEM_BYTES>>>(x1, x2, out);
}